// round 7
// baseline (speedup 1.0000x reference)
#include <cuda_runtime.h>
#include <cstdint>

// ---------------- problem constants ----------------
#define B_   32
#define H_   168
#define N_   512
#define F_   8
#define P_   24
#define KIN_ (N_ * F_)   // 4096
#define G4N_ (4 * N_)    // 2048
#define MR_  (B_ * H_)   // 5376
#define RGRID 128        // recurrence grid (all co-resident; 128 <= 148 SMs)
#define HS_  516         // hsh row stride (pad: conflict-free LDS.128 phases)

typedef unsigned long long ull;

// ---------------- device scratch (no runtime allocation allowed) ----------------
__device__ float d_xr[(size_t)MR_ * N_];        // 11 MB
__device__ float d_xk[(size_t)MR_ * G4N_];      // 44 MB (includes lstm_b)
__device__ float d_wdec[(size_t)N_ * G4N_];     // 4 MB  (lstm_k + lstm_rk)
__device__ float d_h[2][B_ * N_];               // h[b][n], double buffered
__device__ float d_preds[(size_t)B_ * P_ * N_]; // 1.5 MB
__device__ unsigned int g_arrive;               // monotonic barrier counters
__device__ unsigned int g_release;

// ---------------- tf32 helpers ----------------
__device__ __forceinline__ unsigned f2tf(float x) {
    unsigned r;
    asm("cvt.rna.tf32.f32 %0, %1;" : "=r"(r) : "f"(x));
    return r;
}

// ======================================================================
// Generic C[M,N] = A[M,K] @ B[K,N] + bias[N], tf32 tensor cores.
// Block tile 128x64, 8 warps (4x2), warp tile 32x32, K-tile 32.
// ======================================================================
#define BM 128
#define BN 64
#define BKt 32

__global__ __launch_bounds__(256) void gemm_tf32(
    const float* __restrict__ A, const float* __restrict__ Bw,
    const float* __restrict__ bias, float* __restrict__ C,
    int M, int N, int K)
{
    __shared__ float As[BM][BKt + 4];
    __shared__ float Bs[BKt][BN + 4];

    const int tid  = threadIdx.x;
    const int lane = tid & 31;
    const int warp = tid >> 5;
    const int wm = warp & 3;
    const int wn = warp >> 2;
    const int bm = blockIdx.y, bn = blockIdx.x;
    const int g  = lane >> 2;
    const int tg = lane & 3;

    const float* Ag = A + (size_t)bm * BM * K;
    const float* Bg = Bw + (size_t)bn * BN;

    float acc[2][4][4];
#pragma unroll
    for (int i = 0; i < 2; i++)
#pragma unroll
        for (int j = 0; j < 4; j++)
#pragma unroll
            for (int r = 0; r < 4; r++) acc[i][j][r] = 0.f;

    for (int kt = 0; kt < K; kt += BKt) {
#pragma unroll
        for (int i = 0; i < 4; i++) {
            int f4  = tid + i * 256;
            int row = f4 >> 3;
            int kc  = (f4 & 7) << 2;
            float4 v = *(const float4*)(Ag + (size_t)row * K + kt + kc);
            As[row][kc + 0] = __uint_as_float(f2tf(v.x));
            As[row][kc + 1] = __uint_as_float(f2tf(v.y));
            As[row][kc + 2] = __uint_as_float(f2tf(v.z));
            As[row][kc + 3] = __uint_as_float(f2tf(v.w));
        }
#pragma unroll
        for (int i = 0; i < 2; i++) {
            int f4  = tid + i * 256;
            int row = f4 >> 4;
            int nc  = (f4 & 15) << 2;
            float4 v = *(const float4*)(Bg + (size_t)(kt + row) * N + nc);
            Bs[row][nc + 0] = __uint_as_float(f2tf(v.x));
            Bs[row][nc + 1] = __uint_as_float(f2tf(v.y));
            Bs[row][nc + 2] = __uint_as_float(f2tf(v.z));
            Bs[row][nc + 3] = __uint_as_float(f2tf(v.w));
        }
        __syncthreads();

#pragma unroll
        for (int ks = 0; ks < 4; ks++) {
            const int k0 = ks * 8;
            unsigned a[2][4], b[4][2];
#pragma unroll
            for (int mi = 0; mi < 2; mi++) {
                int m0 = wm * 32 + mi * 16;
                a[mi][0] = __float_as_uint(As[m0 + g    ][k0 + tg    ]);
                a[mi][1] = __float_as_uint(As[m0 + g + 8][k0 + tg    ]);
                a[mi][2] = __float_as_uint(As[m0 + g    ][k0 + tg + 4]);
                a[mi][3] = __float_as_uint(As[m0 + g + 8][k0 + tg + 4]);
            }
#pragma unroll
            for (int ni = 0; ni < 4; ni++) {
                int n0 = wn * 32 + ni * 8;
                b[ni][0] = __float_as_uint(Bs[k0 + tg    ][n0 + g]);
                b[ni][1] = __float_as_uint(Bs[k0 + tg + 4][n0 + g]);
            }
#pragma unroll
            for (int mi = 0; mi < 2; mi++)
#pragma unroll
                for (int ni = 0; ni < 4; ni++)
                    asm volatile(
                        "mma.sync.aligned.m16n8k8.row.col.f32.tf32.tf32.f32 "
                        "{%0,%1,%2,%3},{%4,%5,%6,%7},{%8,%9},{%0,%1,%2,%3};"
                        : "+f"(acc[mi][ni][0]), "+f"(acc[mi][ni][1]),
                          "+f"(acc[mi][ni][2]), "+f"(acc[mi][ni][3])
                        : "r"(a[mi][0]), "r"(a[mi][1]), "r"(a[mi][2]), "r"(a[mi][3]),
                          "r"(b[ni][0]), "r"(b[ni][1]));
        }
        __syncthreads();
    }

#pragma unroll
    for (int mi = 0; mi < 2; mi++) {
        int r0 = bm * BM + wm * 32 + mi * 16 + g;
#pragma unroll
        for (int ni = 0; ni < 4; ni++) {
            int c0 = bn * BN + wn * 32 + ni * 8 + tg * 2;
            float b0 = bias[c0], b1 = bias[c0 + 1];
            *(float2*)(C + (size_t)r0 * N + c0) =
                make_float2(acc[mi][ni][0] + b0, acc[mi][ni][1] + b1);
            *(float2*)(C + (size_t)(r0 + 8) * N + c0) =
                make_float2(acc[mi][ni][2] + b0, acc[mi][ni][3] + b1);
        }
    }
}

// ======================================================================
// Wdec = lstm_k + lstm_rk (elementwise, float4)
// ======================================================================
__global__ void add_w(const float* __restrict__ a, const float* __restrict__ b,
                      float* __restrict__ o, int n4)
{
    int i = blockIdx.x * blockDim.x + threadIdx.x;
    if (i < n4) {
        float4 x = ((const float4*)a)[i];
        float4 y = ((const float4*)b)[i];
        ((float4*)o)[i] = make_float4(x.x + y.x, x.y + y.y, x.z + y.z, x.w + y.w);
    }
}

// ======================================================================
// Persistent recurrence kernel (R7):
//  - 128 blocks x 512 threads (16 warps = 4/SMSP)
//  - block j owns hidden columns [4j, 4j+4)  (16 z-columns across 4 gates)
//  - W enc/dec slices staged in SHARED once, reused 192 steps
//  - split-K x4: warp = (kg 0..3, g 0..3), 128 k-iters each
//  - 4 independent FFMA2 accumulator chains per thread (len 64)
//  - acq/rel grid barrier (no MEMBAR.GPU)
// ======================================================================
__device__ __forceinline__ void grid_barrier()
{
    __syncthreads();
    if (threadIdx.x == 0) {
        unsigned my;
        asm volatile("atom.add.release.gpu.global.u32 %0, [%1], 1;"
                     : "=r"(my) : "l"(&g_arrive) : "memory");
        my += 1u;
        unsigned need = (my + RGRID - 1u) / RGRID;
        if ((my % RGRID) == 0u) {
            asm volatile("red.add.release.gpu.global.u32 [%0], 1;"
                         :: "l"(&g_release) : "memory");
        } else {
            unsigned v;
            do {
                asm volatile("ld.acquire.gpu.global.u32 %0, [%1];"
                             : "=r"(v) : "l"(&g_release) : "memory");
                if (v >= need) break;
                __nanosleep(32);
            } while (true);
        }
    }
    __syncthreads();
}

__device__ __forceinline__ float sigf(float x) { return 1.f / (1.f + expf(-x)); }

__global__ __launch_bounds__(512, 1) void recurrence(
    const float* __restrict__ Wenc,   // lstm_rk [512][2048]
    const float* __restrict__ Wdec,   // [512][2048]
    const float* __restrict__ xk,     // [B*H][2048] (bias folded in)
    const float* __restrict__ lb,     // lstm_b [2048]
    float* __restrict__ preds)        // [B][P][N]
{
    extern __shared__ float sm[];
    float* wEnc = sm;                  //  8192 floats (512 x 16)
    float* wDec = sm + 8192;           //  8192 floats
    float* hsh  = sm + 16384;          // 32 x 516 = 16512 floats
    float* zsf  = sm + 32896;          // 16 x 32 x 4 = 2048 floats

    const int tid = threadIdx.x;
    const int b   = tid & 31;
    const int g   = (tid >> 5) & 3;
    const int kg  = tid >> 7;          // split-K group (0..3)
    const int nc0 = blockIdx.x * 4;

    // ---- stage W slices into shared (once, reused 192 steps) ----
    for (int i = tid; i < 2048; i += 512) {
        int k = i >> 2, gg = i & 3;
        *(float4*)&wEnc[k * 16 + gg * 4] =
            *(const float4*)(Wenc + (size_t)k * G4N_ + gg * 512 + nc0);
        *(float4*)&wDec[k * 16 + gg * 4] =
            *(const float4*)(Wdec + (size_t)k * G4N_ + gg * 512 + nc0);
    }

    // ---- init ----
    const int cu = tid >> 5;           // update-role column (valid for tid<128)
    float lbr[4], cst = 0.f;
    if (tid < 128) {
        d_h[0][(size_t)b * N_ + nc0 + cu] = 0.f;
#pragma unroll
        for (int q = 0; q < 4; q++) lbr[q] = lb[q * 512 + nc0 + cu];
    }
    grid_barrier();

    for (int s = 0; s < H_ + P_; s++) {
        // ---- stage h[b][n] -> hsh (stride 516), bypass L1 ----
        const float4* hg = (const float4*)d_h[s & 1];
#pragma unroll
        for (int i = 0; i < 8; i++) {
            int idx = tid + i * 512;       // idx = b*128 + n4
            int bb = idx >> 7, n4 = idx & 127;
            float4 v = __ldcg(hg + idx);
            *(float4*)&hsh[bb * HS_ + n4 * 4] = v;
        }
        // ---- prefetch per-step additive term (xk row or lstm_b) ----
        float pf[4];
        if (tid < 128) {
            if (s < H_) {
                const float* xp = xk + ((size_t)b * H_ + s) * G4N_ + nc0 + cu;
                pf[0] = __ldg(xp);
                pf[1] = __ldg(xp + 512);
                pf[2] = __ldg(xp + 1024);
                pf[3] = __ldg(xp + 1536);
            } else {
                pf[0] = lbr[0]; pf[1] = lbr[1]; pf[2] = lbr[2]; pf[3] = lbr[3];
            }
        }
        __syncthreads();

        // ---- z partial: 4 cols (gate g), k-range [kg*128, kg*128+128) ----
        // 4 independent FFMA2 chains (a01/a23 x 2 k-interleaved sets)
        const float* Wb = (s < H_) ? wEnc : wDec;
        const float* wp = Wb + g * 4 + (kg * 128) * 16;
        const float* hr = hsh + b * HS_ + kg * 128;
        ull a01[2] = {0ull, 0ull}, a23[2] = {0ull, 0ull};
#pragma unroll 8
        for (int kk = 0; kk < 128; kk += 4) {
            float4 h4 = *(const float4*)(hr + kk);
            const int sel = (kk >> 2) & 1;
#pragma unroll
            for (int j = 0; j < 4; j++) {
                ulonglong2 w = *(const ulonglong2*)(wp + (kk + j) * 16);
                float hv = (j == 0) ? h4.x : (j == 1) ? h4.y : (j == 2) ? h4.z : h4.w;
                ull hh;
                asm("mov.b64 %0, {%1,%1};" : "=l"(hh) : "f"(hv));
                asm("fma.rn.f32x2 %0, %1, %2, %0;" : "+l"(a01[sel]) : "l"(hh), "l"(w.x));
                asm("fma.rn.f32x2 %0, %1, %2, %0;" : "+l"(a23[sel]) : "l"(hh), "l"(w.y));
            }
        }
        // combine chains, stash partials
        {
            float x0, x1, x2, x3, y0, y1, y2, y3;
            asm("mov.b64 {%0,%1}, %2;" : "=f"(x0), "=f"(x1) : "l"(a01[0]));
            asm("mov.b64 {%0,%1}, %2;" : "=f"(y0), "=f"(y1) : "l"(a01[1]));
            asm("mov.b64 {%0,%1}, %2;" : "=f"(x2), "=f"(x3) : "l"(a23[0]));
            asm("mov.b64 {%0,%1}, %2;" : "=f"(y2), "=f"(y3) : "l"(a23[1]));
            float4* zp = (float4*)&zsf[((kg * 4 + g) * 32 + b) * 4];
            *zp = make_float4(x0 + y0, x1 + y1, x2 + y2, x3 + y3);
        }
        __syncthreads();

        // ---- cell update: thread (b, cu) handles hidden col nc0+cu ----
        if (tid < 128) {
            float z[4];
#pragma unroll
            for (int q = 0; q < 4; q++) {
                float acc = pf[q];
#pragma unroll
                for (int kq = 0; kq < 4; kq++)
                    acc += zsf[(((kq * 4 + q) * 32 + b) * 4) + cu];
                z[q] = acc;
            }
            float ii = sigf(z[0]), ff = sigf(z[1]);
            float gg = tanhf(z[2]), oo = sigf(z[3]);
            cst = ff * cst + ii * gg;
            float hn = oo * tanhf(cst);
            d_h[(s + 1) & 1][(size_t)b * N_ + nc0 + cu] = hn;
            if (s >= H_)
                preds[((size_t)b * P_ + (s - H_)) * N_ + nc0 + cu] = hn;
        }
        grid_barrier();
    }
}

// ======================================================================
// launch
// ======================================================================
extern "C" void kernel_launch(void* const* d_in, const int* in_sizes, int n_in,
                              void* d_out, int out_size)
{
    const float* x       = (const float*)d_in[0];
    const float* conv_w  = (const float*)d_in[1];
    const float* conv_b  = (const float*)d_in[2];
    const float* lstm_k  = (const float*)d_in[3];
    const float* lstm_rk = (const float*)d_in[4];
    const float* lstm_b  = (const float*)d_in[5];
    const float* dense_w = (const float*)d_in[6];
    const float* dense_b = (const float*)d_in[7];
    float* out = (float*)d_out;

    float *xr, *xk, *wdec, *preds;
    cudaGetSymbolAddress((void**)&xr,    d_xr);
    cudaGetSymbolAddress((void**)&xk,    d_xk);
    cudaGetSymbolAddress((void**)&wdec,  d_wdec);
    cudaGetSymbolAddress((void**)&preds, d_preds);

    const int RSMEM = (8192 + 8192 + 16512 + 2048) * 4;  // 139776 B
    cudaFuncSetAttribute(recurrence, cudaFuncAttributeMaxDynamicSharedMemorySize, RSMEM);

    // 1) xr = reshape(x) @ conv_w + conv_b     [5376,4096]x[4096,512]
    {
        dim3 grid(N_ / BN, MR_ / BM);
        gemm_tf32<<<grid, 256>>>(x, conv_w, conv_b, xr, MR_, N_, KIN_);
    }
    // 2) xk = xr @ lstm_k + lstm_b             [5376,512]x[512,2048]
    {
        dim3 grid(G4N_ / BN, MR_ / BM);
        gemm_tf32<<<grid, 256>>>(xr, lstm_k, lstm_b, xk, MR_, G4N_, N_);
    }
    // 3) Wdec = lstm_k + lstm_rk
    {
        int n4 = (N_ * G4N_) / 4;
        add_w<<<(n4 + 255) / 256, 256>>>(lstm_k, lstm_rk, wdec, n4);
    }
    // 4) encoder (168 steps) + decoder (24 steps), persistent
    recurrence<<<RGRID, 512, RSMEM>>>(lstm_rk, wdec, xk, lstm_b, preds);
    // 5) out = preds @ dense_w + dense_b       [768,512]x[512,512]
    {
        dim3 grid(N_ / BN, (B_ * P_) / BM);
        gemm_tf32<<<grid, 256>>>(preds, dense_w, dense_b, out, B_ * P_, N_, N_);
    }
}

// round 8
// speedup vs baseline: 1.1504x; 1.1504x over previous
#include <cuda_runtime.h>
#include <cstdint>

// ---------------- problem constants ----------------
#define B_   32
#define H_   168
#define N_   512
#define F_   8
#define P_   24
#define KIN_ (N_ * F_)   // 4096
#define G4N_ (4 * N_)    // 2048
#define MR_  (B_ * H_)   // 5376
#define RGRID 128        // recurrence grid (all co-resident; 128 <= 148 SMs)
#define HS_  516         // hsh row stride (conflict-free A-frag loads: 516 % 32 == 4)
#define WS_  24          // W smem row stride (conflict-free B-frag loads)
#define PS_  36          // psum b-stride (conflict-free partial STS/LDS)

typedef unsigned long long ull;

// ---------------- device scratch (no runtime allocation allowed) ----------------
__device__ float d_xr[(size_t)MR_ * N_];        // 11 MB
__device__ float d_xk[(size_t)MR_ * G4N_];      // 44 MB (includes lstm_b)
__device__ float d_wdec[(size_t)N_ * G4N_];     // 4 MB  (lstm_k + lstm_rk)
__device__ float d_h[2][B_ * N_];               // h[b][n], double buffered
__device__ float d_preds[(size_t)B_ * P_ * N_]; // 1.5 MB
__device__ unsigned int g_arrive;               // monotonic barrier counters
__device__ unsigned int g_release;

// ---------------- tf32 helpers ----------------
__device__ __forceinline__ unsigned f2tf(float x) {
    unsigned r;
    asm("cvt.rna.tf32.f32 %0, %1;" : "=r"(r) : "f"(x));
    return r;
}

__device__ __forceinline__ void mma_tf32(float* c, const unsigned* a,
                                         unsigned b0, unsigned b1) {
    asm volatile(
        "mma.sync.aligned.m16n8k8.row.col.f32.tf32.tf32.f32 "
        "{%0,%1,%2,%3},{%4,%5,%6,%7},{%8,%9},{%0,%1,%2,%3};"
        : "+f"(c[0]), "+f"(c[1]), "+f"(c[2]), "+f"(c[3])
        : "r"(a[0]), "r"(a[1]), "r"(a[2]), "r"(a[3]), "r"(b0), "r"(b1));
}

// ======================================================================
// Generic C[M,N] = A[M,K] @ B[K,N] + bias[N], tf32 tensor cores.
// Block tile 128x64, 8 warps (4x2), warp tile 32x32, K-tile 32.
// ======================================================================
#define BM 128
#define BN 64
#define BKt 32

__global__ __launch_bounds__(256) void gemm_tf32(
    const float* __restrict__ A, const float* __restrict__ Bw,
    const float* __restrict__ bias, float* __restrict__ C,
    int M, int N, int K)
{
    __shared__ float As[BM][BKt + 4];
    __shared__ float Bs[BKt][BN + 4];

    const int tid  = threadIdx.x;
    const int lane = tid & 31;
    const int warp = tid >> 5;
    const int wm = warp & 3;
    const int wn = warp >> 2;
    const int bm = blockIdx.y, bn = blockIdx.x;
    const int g  = lane >> 2;
    const int tg = lane & 3;

    const float* Ag = A + (size_t)bm * BM * K;
    const float* Bg = Bw + (size_t)bn * BN;

    float acc[2][4][4];
#pragma unroll
    for (int i = 0; i < 2; i++)
#pragma unroll
        for (int j = 0; j < 4; j++)
#pragma unroll
            for (int r = 0; r < 4; r++) acc[i][j][r] = 0.f;

    for (int kt = 0; kt < K; kt += BKt) {
#pragma unroll
        for (int i = 0; i < 4; i++) {
            int f4  = tid + i * 256;
            int row = f4 >> 3;
            int kc  = (f4 & 7) << 2;
            float4 v = *(const float4*)(Ag + (size_t)row * K + kt + kc);
            As[row][kc + 0] = __uint_as_float(f2tf(v.x));
            As[row][kc + 1] = __uint_as_float(f2tf(v.y));
            As[row][kc + 2] = __uint_as_float(f2tf(v.z));
            As[row][kc + 3] = __uint_as_float(f2tf(v.w));
        }
#pragma unroll
        for (int i = 0; i < 2; i++) {
            int f4  = tid + i * 256;
            int row = f4 >> 4;
            int nc  = (f4 & 15) << 2;
            float4 v = *(const float4*)(Bg + (size_t)(kt + row) * N + nc);
            Bs[row][nc + 0] = __uint_as_float(f2tf(v.x));
            Bs[row][nc + 1] = __uint_as_float(f2tf(v.y));
            Bs[row][nc + 2] = __uint_as_float(f2tf(v.z));
            Bs[row][nc + 3] = __uint_as_float(f2tf(v.w));
        }
        __syncthreads();

#pragma unroll
        for (int ks = 0; ks < 4; ks++) {
            const int k0 = ks * 8;
            unsigned a[2][4], b[4][2];
#pragma unroll
            for (int mi = 0; mi < 2; mi++) {
                int m0 = wm * 32 + mi * 16;
                a[mi][0] = __float_as_uint(As[m0 + g    ][k0 + tg    ]);
                a[mi][1] = __float_as_uint(As[m0 + g + 8][k0 + tg    ]);
                a[mi][2] = __float_as_uint(As[m0 + g    ][k0 + tg + 4]);
                a[mi][3] = __float_as_uint(As[m0 + g + 8][k0 + tg + 4]);
            }
#pragma unroll
            for (int ni = 0; ni < 4; ni++) {
                int n0 = wn * 32 + ni * 8;
                b[ni][0] = __float_as_uint(Bs[k0 + tg    ][n0 + g]);
                b[ni][1] = __float_as_uint(Bs[k0 + tg + 4][n0 + g]);
            }
#pragma unroll
            for (int mi = 0; mi < 2; mi++)
#pragma unroll
                for (int ni = 0; ni < 4; ni++)
                    asm volatile(
                        "mma.sync.aligned.m16n8k8.row.col.f32.tf32.tf32.f32 "
                        "{%0,%1,%2,%3},{%4,%5,%6,%7},{%8,%9},{%0,%1,%2,%3};"
                        : "+f"(acc[mi][ni][0]), "+f"(acc[mi][ni][1]),
                          "+f"(acc[mi][ni][2]), "+f"(acc[mi][ni][3])
                        : "r"(a[mi][0]), "r"(a[mi][1]), "r"(a[mi][2]), "r"(a[mi][3]),
                          "r"(b[ni][0]), "r"(b[ni][1]));
        }
        __syncthreads();
    }

#pragma unroll
    for (int mi = 0; mi < 2; mi++) {
        int r0 = bm * BM + wm * 32 + mi * 16 + g;
#pragma unroll
        for (int ni = 0; ni < 4; ni++) {
            int c0 = bn * BN + wn * 32 + ni * 8 + tg * 2;
            float b0 = bias[c0], b1 = bias[c0 + 1];
            *(float2*)(C + (size_t)r0 * N + c0) =
                make_float2(acc[mi][ni][0] + b0, acc[mi][ni][1] + b1);
            *(float2*)(C + (size_t)(r0 + 8) * N + c0) =
                make_float2(acc[mi][ni][2] + b0, acc[mi][ni][3] + b1);
        }
    }
}

// ======================================================================
// Wdec = lstm_k + lstm_rk (elementwise, float4)
// ======================================================================
__global__ void add_w(const float* __restrict__ a, const float* __restrict__ b,
                      float* __restrict__ o, int n4)
{
    int i = blockIdx.x * blockDim.x + threadIdx.x;
    if (i < n4) {
        float4 x = ((const float4*)a)[i];
        float4 y = ((const float4*)b)[i];
        ((float4*)o)[i] = make_float4(x.x + y.x, x.y + y.y, x.z + y.z, x.w + y.w);
    }
}

// ======================================================================
// Persistent recurrence kernel (R8): tensor-core step GEMM.
//  - 128 blocks x 512 threads; block owns 4 hidden cols -> 16 z-cols
//  - per step: z[32x16] = h[32x512] @ Wslice[512x16] via m16n8k8 tf32 mma
//  - 3-term hi/lo tf32 compensation => effectively fp32 accurate
//  - 16 warps = (kg 0..7 k-split, mi 0..1 row-half); psum reduce in smem
//  - W fp32 in smem (stride 24), staged once; h staged per step (ldcg)
// ======================================================================
__device__ __forceinline__ void grid_barrier()
{
    __syncthreads();
    if (threadIdx.x == 0) {
        unsigned my;
        asm volatile("atom.add.release.gpu.global.u32 %0, [%1], 1;"
                     : "=r"(my) : "l"(&g_arrive) : "memory");
        my += 1u;
        unsigned need = (my + RGRID - 1u) / RGRID;
        if ((my % RGRID) == 0u) {
            asm volatile("red.add.release.gpu.global.u32 [%0], 1;"
                         :: "l"(&g_release) : "memory");
        } else {
            unsigned v;
            do {
                asm volatile("ld.acquire.gpu.global.u32 %0, [%1];"
                             : "=r"(v) : "l"(&g_release) : "memory");
                if (v >= need) break;
                __nanosleep(32);
            } while (true);
        }
    }
    __syncthreads();
}

__device__ __forceinline__ float sigf(float x) { return 1.f / (1.f + expf(-x)); }

__global__ __launch_bounds__(512, 1) void recurrence(
    const float* __restrict__ Wenc,   // lstm_rk [512][2048]
    const float* __restrict__ Wdec,   // [512][2048]
    const float* __restrict__ xk,     // [B*H][2048] (bias folded in)
    const float* __restrict__ lb,     // lstm_b [2048]
    float* __restrict__ preds)        // [B][P][N]
{
    extern __shared__ float sm[];
    float* wEnc = sm;                       // 512*24 = 12288 floats
    float* wDec = sm + 12288;               // 12288 floats
    float* hsh  = sm + 24576;               // 32*516 = 16512 floats
    float* psum = sm + 41088;               // 8*16*36 = 4608 floats

    const int tid  = threadIdx.x;
    const int lane = tid & 31;
    const int warp = tid >> 5;
    const int g    = lane >> 2;
    const int tg   = lane & 3;
    const int kg   = warp & 7;     // k-split group (k in [kg*64, kg*64+64))
    const int mi   = warp >> 3;    // row half (b rows [mi*16, mi*16+16))
    const int m0   = mi * 16;
    const int nc0  = blockIdx.x * 4;

    // ---- stage W slices into shared once (stride 24; col n = gate*4 + c) ----
    for (int i = tid; i < 2048; i += 512) {
        int k = i >> 2, gate = i & 3;
        *(float4*)&wEnc[k * WS_ + gate * 4] =
            *(const float4*)(Wenc + (size_t)k * G4N_ + gate * 512 + nc0);
        *(float4*)&wDec[k * WS_ + gate * 4] =
            *(const float4*)(Wdec + (size_t)k * G4N_ + gate * 512 + nc0);
    }

    // ---- init (update-role threads: tid<128, b = tid&31, cu = tid>>5) ----
    const int b  = tid & 31;
    const int cu = tid >> 5;
    float lbr[4], cst = 0.f;
    if (tid < 128) {
        d_h[0][(size_t)b * N_ + nc0 + cu] = 0.f;
#pragma unroll
        for (int q = 0; q < 4; q++) lbr[q] = lb[q * 512 + nc0 + cu];
    }
    grid_barrier();

    for (int s = 0; s < H_ + P_; s++) {
        // ---- stage h[b][n] -> hsh (stride 516), bypass L1 ----
        const float4* hg = (const float4*)d_h[s & 1];
#pragma unroll
        for (int i = 0; i < 8; i++) {
            int idx = tid + i * 512;       // idx = bb*128 + n4
            int bb = idx >> 7, n4 = idx & 127;
            float4 v = __ldcg(hg + idx);
            *(float4*)&hsh[bb * HS_ + n4 * 4] = v;
        }
        // ---- prefetch per-step additive term (xk row or lstm_b) ----
        float pf[4];
        if (tid < 128) {
            if (s < H_) {
                const float* xp = xk + ((size_t)b * H_ + s) * G4N_ + nc0 + cu;
                pf[0] = __ldg(xp);
                pf[1] = __ldg(xp + 512);
                pf[2] = __ldg(xp + 1024);
                pf[3] = __ldg(xp + 1536);
            } else {
                pf[0] = lbr[0]; pf[1] = lbr[1]; pf[2] = lbr[2]; pf[3] = lbr[3];
            }
        }
        __syncthreads();

        // ---- tensor-core partial GEMM: rows [m0,m0+16), k-slice [kg*64,+64) ----
        const float* Ws = (s < H_) ? wEnc : wDec;
        float acc0[4] = {0.f, 0.f, 0.f, 0.f};
        float acc1[4] = {0.f, 0.f, 0.f, 0.f};
#pragma unroll
        for (int f = 0; f < 8; f++) {
            const int k0 = kg * 64 + f * 8;
            // A frag (fp32 -> hi/lo tf32)
            float a0 = hsh[(m0 + g    ) * HS_ + k0 + tg    ];
            float a1 = hsh[(m0 + g + 8) * HS_ + k0 + tg    ];
            float a2 = hsh[(m0 + g    ) * HS_ + k0 + tg + 4];
            float a3 = hsh[(m0 + g + 8) * HS_ + k0 + tg + 4];
            unsigned ahi[4], alo[4];
            ahi[0] = f2tf(a0); alo[0] = f2tf(a0 - __uint_as_float(ahi[0]));
            ahi[1] = f2tf(a1); alo[1] = f2tf(a1 - __uint_as_float(ahi[1]));
            ahi[2] = f2tf(a2); alo[2] = f2tf(a2 - __uint_as_float(ahi[2]));
            ahi[3] = f2tf(a3); alo[3] = f2tf(a3 - __uint_as_float(ahi[3]));
            // B frags: n-frag 0 (cols 0..7), n-frag 1 (cols 8..15)
            float b0f = Ws[(k0 + tg    ) * WS_ + g];
            float b1f = Ws[(k0 + tg + 4) * WS_ + g];
            float b2f = Ws[(k0 + tg    ) * WS_ + 8 + g];
            float b3f = Ws[(k0 + tg + 4) * WS_ + 8 + g];
            unsigned bh0 = f2tf(b0f), bl0 = f2tf(b0f - __uint_as_float(bh0));
            unsigned bh1 = f2tf(b1f), bl1 = f2tf(b1f - __uint_as_float(bh1));
            unsigned bh2 = f2tf(b2f), bl2 = f2tf(b2f - __uint_as_float(bh2));
            unsigned bh3 = f2tf(b3f), bl3 = f2tf(b3f - __uint_as_float(bh3));
            // 3-term compensated accumulate
            mma_tf32(acc0, ahi, bh0, bh1);
            mma_tf32(acc0, alo, bh0, bh1);
            mma_tf32(acc0, ahi, bl0, bl1);
            mma_tf32(acc1, ahi, bh2, bh3);
            mma_tf32(acc1, alo, bh2, bh3);
            mma_tf32(acc1, ahi, bl2, bl3);
        }
        // ---- stash partials: psum[(kg*16 + n)*36 + b], conflict-free ----
        {
            const int c0 = tg * 2, r0 = m0 + g;
            psum[(kg * 16 + c0        ) * PS_ + r0    ] = acc0[0];
            psum[(kg * 16 + c0 + 1    ) * PS_ + r0    ] = acc0[1];
            psum[(kg * 16 + c0        ) * PS_ + r0 + 8] = acc0[2];
            psum[(kg * 16 + c0 + 1    ) * PS_ + r0 + 8] = acc0[3];
            psum[(kg * 16 + 8 + c0    ) * PS_ + r0    ] = acc1[0];
            psum[(kg * 16 + 8 + c0 + 1) * PS_ + r0    ] = acc1[1];
            psum[(kg * 16 + 8 + c0    ) * PS_ + r0 + 8] = acc1[2];
            psum[(kg * 16 + 8 + c0 + 1) * PS_ + r0 + 8] = acc1[3];
        }
        __syncthreads();

        // ---- cell update: thread (b, cu) handles hidden col nc0+cu ----
        if (tid < 128) {
            float z[4];
#pragma unroll
            for (int q = 0; q < 4; q++) {
                const int n = q * 4 + cu;    // z-col = gate*4 + hidden-col
                float accv = pf[q];
#pragma unroll
                for (int kk = 0; kk < 8; kk++)
                    accv += psum[(kk * 16 + n) * PS_ + b];
                z[q] = accv;
            }
            float ii = sigf(z[0]), ff = sigf(z[1]);
            float gg = tanhf(z[2]), oo = sigf(z[3]);
            cst = ff * cst + ii * gg;
            float hn = oo * tanhf(cst);
            d_h[(s + 1) & 1][(size_t)b * N_ + nc0 + cu] = hn;
            if (s >= H_)
                preds[((size_t)b * P_ + (s - H_)) * N_ + nc0 + cu] = hn;
        }
        grid_barrier();
    }
}

// ======================================================================
// launch
// ======================================================================
extern "C" void kernel_launch(void* const* d_in, const int* in_sizes, int n_in,
                              void* d_out, int out_size)
{
    const float* x       = (const float*)d_in[0];
    const float* conv_w  = (const float*)d_in[1];
    const float* conv_b  = (const float*)d_in[2];
    const float* lstm_k  = (const float*)d_in[3];
    const float* lstm_rk = (const float*)d_in[4];
    const float* lstm_b  = (const float*)d_in[5];
    const float* dense_w = (const float*)d_in[6];
    const float* dense_b = (const float*)d_in[7];
    float* out = (float*)d_out;

    float *xr, *xk, *wdec, *preds;
    cudaGetSymbolAddress((void**)&xr,    d_xr);
    cudaGetSymbolAddress((void**)&xk,    d_xk);
    cudaGetSymbolAddress((void**)&wdec,  d_wdec);
    cudaGetSymbolAddress((void**)&preds, d_preds);

    const int RSMEM = (12288 + 12288 + 16512 + 4608) * 4;  // 182784 B
    cudaFuncSetAttribute(recurrence, cudaFuncAttributeMaxDynamicSharedMemorySize, RSMEM);

    // 1) xr = reshape(x) @ conv_w + conv_b     [5376,4096]x[4096,512]
    {
        dim3 grid(N_ / BN, MR_ / BM);
        gemm_tf32<<<grid, 256>>>(x, conv_w, conv_b, xr, MR_, N_, KIN_);
    }
    // 2) xk = xr @ lstm_k + lstm_b             [5376,512]x[512,2048]
    {
        dim3 grid(G4N_ / BN, MR_ / BM);
        gemm_tf32<<<grid, 256>>>(xr, lstm_k, lstm_b, xk, MR_, G4N_, N_);
    }
    // 3) Wdec = lstm_k + lstm_rk
    {
        int n4 = (N_ * G4N_) / 4;
        add_w<<<(n4 + 255) / 256, 256>>>(lstm_k, lstm_rk, wdec, n4);
    }
    // 4) encoder (168 steps) + decoder (24 steps), persistent
    recurrence<<<RGRID, 512, RSMEM>>>(lstm_rk, wdec, xk, lstm_b, preds);
    // 5) out = preds @ dense_w + dense_b       [768,512]x[512,512]
    {
        dim3 grid(N_ / BN, (B_ * P_) / BM);
        gemm_tf32<<<grid, 256>>>(preds, dense_w, dense_b, out, B_ * P_, N_, N_);
    }
}

// round 9
// speedup vs baseline: 1.3959x; 1.2134x over previous
#include <cuda_runtime.h>
#include <cstdint>

// ---------------- problem constants ----------------
#define B_   32
#define H_   168
#define N_   512
#define F_   8
#define P_   24
#define KIN_ (N_ * F_)   // 4096
#define G4N_ (4 * N_)    // 2048
#define MR_  (B_ * H_)   // 5376
#define RGRID 128        // recurrence grid (all co-resident; 128 <= 148 SMs)
#define HS_  516         // hsh row stride (conflict-free A-frag loads)
#define WS_  24          // W smem row stride (conflict-free B-frag loads)
#define PS_  36          // psum b-stride (conflict-free partial STS/LDS)

typedef unsigned long long ull;

// ---------------- device scratch (no runtime allocation allowed) ----------------
__device__ float d_xr[(size_t)MR_ * N_];        // 11 MB
__device__ float d_xk[(size_t)MR_ * G4N_];      // 44 MB (includes lstm_b)
__device__ float d_wdec[(size_t)N_ * G4N_];     // 4 MB  (lstm_k + lstm_rk)
__device__ float d_h[2][B_ * N_];               // h[b][n], double buffered
__device__ float d_preds[(size_t)B_ * P_ * N_]; // 1.5 MB
__device__ ull g_arrive64;                      // monotonic barrier counter

// ---------------- tf32 helpers ----------------
__device__ __forceinline__ unsigned f2tf(float x) {
    unsigned r;
    asm("cvt.rna.tf32.f32 %0, %1;" : "=r"(r) : "f"(x));
    return r;
}

__device__ __forceinline__ void mma_tf32(float* c, const unsigned* a,
                                         unsigned b0, unsigned b1) {
    asm volatile(
        "mma.sync.aligned.m16n8k8.row.col.f32.tf32.tf32.f32 "
        "{%0,%1,%2,%3},{%4,%5,%6,%7},{%8,%9},{%0,%1,%2,%3};"
        : "+f"(c[0]), "+f"(c[1]), "+f"(c[2]), "+f"(c[3])
        : "r"(a[0]), "r"(a[1]), "r"(a[2]), "r"(a[3]), "r"(b0), "r"(b1));
}

// ======================================================================
// C[M,N] = A[M,K] @ B[K,N] + bias[N], tf32 mma, double-buffered pipeline.
// Block tile 128x64, 8 warps (4x2), warp tile 32x32, K-tile 32.
// ======================================================================
#define BM 128
#define BN 64
#define BKt 32

__global__ __launch_bounds__(256) void gemm_tf32(
    const float* __restrict__ A, const float* __restrict__ Bw,
    const float* __restrict__ bias, float* __restrict__ C,
    int M, int N, int K)
{
    __shared__ float As[2][BM][BKt + 4];
    __shared__ float Bs[2][BKt][BN + 4];

    const int tid  = threadIdx.x;
    const int lane = tid & 31;
    const int warp = tid >> 5;
    const int wm = warp & 3;
    const int wn = warp >> 2;
    const int bm = blockIdx.y, bn = blockIdx.x;
    const int g  = lane >> 2;
    const int tg = lane & 3;

    const float* Ag = A + (size_t)bm * BM * K;
    const float* Bg = Bw + (size_t)bn * BN;

    // per-thread staging coordinates
    int arow[4], akc[4];
#pragma unroll
    for (int i = 0; i < 4; i++) {
        int f4 = tid + i * 256;
        arow[i] = f4 >> 3;
        akc[i]  = (f4 & 7) << 2;
    }
    int brow[2], bnc[2];
#pragma unroll
    for (int i = 0; i < 2; i++) {
        int f4 = tid + i * 256;
        brow[i] = f4 >> 4;
        bnc[i]  = (f4 & 15) << 2;
    }

    float acc[2][4][4];
#pragma unroll
    for (int i = 0; i < 2; i++)
#pragma unroll
        for (int j = 0; j < 4; j++)
#pragma unroll
            for (int r = 0; r < 4; r++) acc[i][j][r] = 0.f;

    float4 ra[4], rb[2];
#pragma unroll
    for (int i = 0; i < 4; i++)
        ra[i] = *(const float4*)(Ag + (size_t)arow[i] * K + akc[i]);
#pragma unroll
    for (int i = 0; i < 2; i++)
        rb[i] = *(const float4*)(Bg + (size_t)brow[i] * N + bnc[i]);

    const int T = K / BKt;
    int buf = 0;
    // store tile 0
#pragma unroll
    for (int i = 0; i < 4; i++) {
        As[0][arow[i]][akc[i] + 0] = __uint_as_float(f2tf(ra[i].x));
        As[0][arow[i]][akc[i] + 1] = __uint_as_float(f2tf(ra[i].y));
        As[0][arow[i]][akc[i] + 2] = __uint_as_float(f2tf(ra[i].z));
        As[0][arow[i]][akc[i] + 3] = __uint_as_float(f2tf(ra[i].w));
    }
#pragma unroll
    for (int i = 0; i < 2; i++) {
        Bs[0][brow[i]][bnc[i] + 0] = __uint_as_float(f2tf(rb[i].x));
        Bs[0][brow[i]][bnc[i] + 1] = __uint_as_float(f2tf(rb[i].y));
        Bs[0][brow[i]][bnc[i] + 2] = __uint_as_float(f2tf(rb[i].z));
        Bs[0][brow[i]][bnc[i] + 3] = __uint_as_float(f2tf(rb[i].w));
    }
    __syncthreads();

    for (int t = 0; t < T; t++) {
        // prefetch next tile into registers (hidden under mma)
        if (t + 1 < T) {
            const int kt = (t + 1) * BKt;
#pragma unroll
            for (int i = 0; i < 4; i++)
                ra[i] = *(const float4*)(Ag + (size_t)arow[i] * K + kt + akc[i]);
#pragma unroll
            for (int i = 0; i < 2; i++)
                rb[i] = *(const float4*)(Bg + (size_t)(kt + brow[i]) * N + bnc[i]);
        }

#pragma unroll
        for (int ks = 0; ks < 4; ks++) {
            const int k0 = ks * 8;
            unsigned a[2][4], b[4][2];
#pragma unroll
            for (int mi = 0; mi < 2; mi++) {
                int m0 = wm * 32 + mi * 16;
                a[mi][0] = __float_as_uint(As[buf][m0 + g    ][k0 + tg    ]);
                a[mi][1] = __float_as_uint(As[buf][m0 + g + 8][k0 + tg    ]);
                a[mi][2] = __float_as_uint(As[buf][m0 + g    ][k0 + tg + 4]);
                a[mi][3] = __float_as_uint(As[buf][m0 + g + 8][k0 + tg + 4]);
            }
#pragma unroll
            for (int ni = 0; ni < 4; ni++) {
                int n0 = wn * 32 + ni * 8;
                b[ni][0] = __float_as_uint(Bs[buf][k0 + tg    ][n0 + g]);
                b[ni][1] = __float_as_uint(Bs[buf][k0 + tg + 4][n0 + g]);
            }
#pragma unroll
            for (int mi = 0; mi < 2; mi++)
#pragma unroll
                for (int ni = 0; ni < 4; ni++)
                    mma_tf32(acc[mi][ni], a[mi], b[ni][0], b[ni][1]);
        }

        if (t + 1 < T) {
            const int nb = buf ^ 1;
#pragma unroll
            for (int i = 0; i < 4; i++) {
                As[nb][arow[i]][akc[i] + 0] = __uint_as_float(f2tf(ra[i].x));
                As[nb][arow[i]][akc[i] + 1] = __uint_as_float(f2tf(ra[i].y));
                As[nb][arow[i]][akc[i] + 2] = __uint_as_float(f2tf(ra[i].z));
                As[nb][arow[i]][akc[i] + 3] = __uint_as_float(f2tf(ra[i].w));
            }
#pragma unroll
            for (int i = 0; i < 2; i++) {
                Bs[nb][brow[i]][bnc[i] + 0] = __uint_as_float(f2tf(rb[i].x));
                Bs[nb][brow[i]][bnc[i] + 1] = __uint_as_float(f2tf(rb[i].y));
                Bs[nb][brow[i]][bnc[i] + 2] = __uint_as_float(f2tf(rb[i].z));
                Bs[nb][brow[i]][bnc[i] + 3] = __uint_as_float(f2tf(rb[i].w));
            }
            __syncthreads();
            buf = nb;
        }
    }

#pragma unroll
    for (int mi = 0; mi < 2; mi++) {
        int r0 = bm * BM + wm * 32 + mi * 16 + g;
#pragma unroll
        for (int ni = 0; ni < 4; ni++) {
            int c0 = bn * BN + wn * 32 + ni * 8 + tg * 2;
            float b0 = bias[c0], b1 = bias[c0 + 1];
            *(float2*)(C + (size_t)r0 * N + c0) =
                make_float2(acc[mi][ni][0] + b0, acc[mi][ni][1] + b1);
            *(float2*)(C + (size_t)(r0 + 8) * N + c0) =
                make_float2(acc[mi][ni][2] + b0, acc[mi][ni][3] + b1);
        }
    }
}

// ======================================================================
// Wdec = lstm_k + lstm_rk (elementwise, float4)
// ======================================================================
__global__ void add_w(const float* __restrict__ a, const float* __restrict__ b,
                      float* __restrict__ o, int n4)
{
    int i = blockIdx.x * blockDim.x + threadIdx.x;
    if (i < n4) {
        float4 x = ((const float4*)a)[i];
        float4 y = ((const float4*)b)[i];
        ((float4*)o)[i] = make_float4(x.x + y.x, x.y + y.y, x.z + y.z, x.w + y.w);
    }
}

// ======================================================================
// Persistent recurrence kernel (R9):
//  - single-counter u64 grid barrier (one L2 round trip fewer per step)
//  - W hi/lo tf32 precomputed in smem (once; re-staged at enc->dec)
//  - lo remainders fed as raw fp32 bits (HW truncation, cutlass fast path)
//  - xk[s+1] prefetched during step s update (DRAM off critical path)
// ======================================================================
__device__ __forceinline__ void grid_barrier()
{
    __syncthreads();
    if (threadIdx.x == 0) {
        ull my;
        asm volatile("atom.add.release.gpu.global.u64 %0, [%1], 1;"
                     : "=l"(my) : "l"(&g_arrive64) : "memory");
        ull target = (my / RGRID + 1ull) * RGRID;
        ull v;
        do {
            asm volatile("ld.acquire.gpu.global.u64 %0, [%1];"
                         : "=l"(v) : "l"(&g_arrive64) : "memory");
            if (v >= target) break;
            __nanosleep(20);
        } while (true);
    }
    __syncthreads();
}

__device__ __forceinline__ float sigf(float x) { return 1.f / (1.f + expf(-x)); }

// stage one W slice (16 cols starting nc0) as hi/lo tf32 into smem
__device__ __forceinline__ void stage_w(const float* __restrict__ W, int nc0,
                                        unsigned* wHi, unsigned* wLo, int tid)
{
    for (int i = tid; i < 2048; i += 512) {
        int k = i >> 2, gate = i & 3;
        float4 w = *(const float4*)(W + (size_t)k * G4N_ + gate * 512 + nc0);
        unsigned h0 = f2tf(w.x), h1 = f2tf(w.y), h2 = f2tf(w.z), h3 = f2tf(w.w);
        unsigned l0 = __float_as_uint(w.x - __uint_as_float(h0));
        unsigned l1 = __float_as_uint(w.y - __uint_as_float(h1));
        unsigned l2 = __float_as_uint(w.z - __uint_as_float(h2));
        unsigned l3 = __float_as_uint(w.w - __uint_as_float(h3));
        uint4* ph = (uint4*)&wHi[k * WS_ + gate * 4];
        uint4* pl = (uint4*)&wLo[k * WS_ + gate * 4];
        *ph = make_uint4(h0, h1, h2, h3);
        *pl = make_uint4(l0, l1, l2, l3);
    }
}

__global__ __launch_bounds__(512, 1) void recurrence(
    const float* __restrict__ Wenc,   // lstm_rk [512][2048]
    const float* __restrict__ Wdec,   // [512][2048]
    const float* __restrict__ xk,     // [B*H][2048] (bias folded in)
    const float* __restrict__ lb,     // lstm_b [2048]
    float* __restrict__ preds)        // [B][P][N]
{
    extern __shared__ float sm[];
    unsigned* wHi = (unsigned*)sm;            // 512*24 = 12288 u32
    unsigned* wLo = (unsigned*)(sm + 12288);  // 12288 u32
    float* hsh    = sm + 24576;               // 32*516 = 16512 floats
    float* psum   = sm + 41088;               // 8*16*36 = 4608 floats

    const int tid  = threadIdx.x;
    const int lane = tid & 31;
    const int warp = tid >> 5;
    const int g    = lane >> 2;
    const int tg   = lane & 3;
    const int kg   = warp & 7;     // k-split group (k in [kg*64, kg*64+64))
    const int mi   = warp >> 3;    // row half
    const int m0   = mi * 16;
    const int nc0  = blockIdx.x * 4;

    // ---- stage encoder W hi/lo once ----
    stage_w(Wenc, nc0, wHi, wLo, tid);

    // ---- init ----
    const int b  = tid & 31;
    const int cu = tid >> 5;
    float lbr[4], cst = 0.f, pf[4];
    if (tid < 128) {
        d_h[0][(size_t)b * N_ + nc0 + cu] = 0.f;
#pragma unroll
        for (int q = 0; q < 4; q++) lbr[q] = lb[q * 512 + nc0 + cu];
        // prefetch xk for step 0
        const float* xp = xk + ((size_t)b * H_) * G4N_ + nc0 + cu;
        pf[0] = __ldg(xp);
        pf[1] = __ldg(xp + 512);
        pf[2] = __ldg(xp + 1024);
        pf[3] = __ldg(xp + 1536);
    }
    grid_barrier();

    for (int s = 0; s < H_ + P_; s++) {
        // re-stage W at encoder->decoder transition (one time)
        if (s == H_) stage_w(Wdec, nc0, wHi, wLo, tid);

        // ---- stage h[b][n] -> hsh (stride 516), bypass L1 ----
        const float4* hg = (const float4*)d_h[s & 1];
#pragma unroll
        for (int i = 0; i < 8; i++) {
            int idx = tid + i * 512;       // idx = bb*128 + n4
            int bb = idx >> 7, n4 = idx & 127;
            float4 v = __ldcg(hg + idx);
            *(float4*)&hsh[bb * HS_ + n4 * 4] = v;
        }
        __syncthreads();

        // ---- tensor-core partial GEMM: rows [m0,m0+16), k-slice [kg*64,+64) ----
        float acc0[4] = {0.f, 0.f, 0.f, 0.f};
        float acc1[4] = {0.f, 0.f, 0.f, 0.f};
#pragma unroll
        for (int f = 0; f < 8; f++) {
            const int k0 = kg * 64 + f * 8;
            // A frag hi/lo (lo = raw fp32 remainder bits)
            float a0 = hsh[(m0 + g    ) * HS_ + k0 + tg    ];
            float a1 = hsh[(m0 + g + 8) * HS_ + k0 + tg    ];
            float a2 = hsh[(m0 + g    ) * HS_ + k0 + tg + 4];
            float a3 = hsh[(m0 + g + 8) * HS_ + k0 + tg + 4];
            unsigned ahi[4], alo[4];
            ahi[0] = f2tf(a0); alo[0] = __float_as_uint(a0 - __uint_as_float(ahi[0]));
            ahi[1] = f2tf(a1); alo[1] = __float_as_uint(a1 - __uint_as_float(ahi[1]));
            ahi[2] = f2tf(a2); alo[2] = __float_as_uint(a2 - __uint_as_float(ahi[2]));
            ahi[3] = f2tf(a3); alo[3] = __float_as_uint(a3 - __uint_as_float(ahi[3]));
            // B frags from precomputed hi/lo
            unsigned bh0 = wHi[(k0 + tg    ) * WS_ + g];
            unsigned bh1 = wHi[(k0 + tg + 4) * WS_ + g];
            unsigned bh2 = wHi[(k0 + tg    ) * WS_ + 8 + g];
            unsigned bh3 = wHi[(k0 + tg + 4) * WS_ + 8 + g];
            unsigned bl0 = wLo[(k0 + tg    ) * WS_ + g];
            unsigned bl1 = wLo[(k0 + tg + 4) * WS_ + g];
            unsigned bl2 = wLo[(k0 + tg    ) * WS_ + 8 + g];
            unsigned bl3 = wLo[(k0 + tg + 4) * WS_ + 8 + g];
            // 3-term compensated accumulate
            mma_tf32(acc0, ahi, bh0, bh1);
            mma_tf32(acc0, alo, bh0, bh1);
            mma_tf32(acc0, ahi, bl0, bl1);
            mma_tf32(acc1, ahi, bh2, bh3);
            mma_tf32(acc1, alo, bh2, bh3);
            mma_tf32(acc1, ahi, bl2, bl3);
        }
        // ---- stash partials ----
        {
            const int c0 = tg * 2, r0 = m0 + g;
            psum[(kg * 16 + c0        ) * PS_ + r0    ] = acc0[0];
            psum[(kg * 16 + c0 + 1    ) * PS_ + r0    ] = acc0[1];
            psum[(kg * 16 + c0        ) * PS_ + r0 + 8] = acc0[2];
            psum[(kg * 16 + c0 + 1    ) * PS_ + r0 + 8] = acc0[3];
            psum[(kg * 16 + 8 + c0    ) * PS_ + r0    ] = acc1[0];
            psum[(kg * 16 + 8 + c0 + 1) * PS_ + r0    ] = acc1[1];
            psum[(kg * 16 + 8 + c0    ) * PS_ + r0 + 8] = acc1[2];
            psum[(kg * 16 + 8 + c0 + 1) * PS_ + r0 + 8] = acc1[3];
        }
        __syncthreads();

        // ---- cell update: thread (b, cu) handles hidden col nc0+cu ----
        if (tid < 128) {
            // prefetch next step's additive term first (hides DRAM latency)
            float pfn[4];
            if (s + 1 < H_) {
                const float* xp = xk + ((size_t)b * H_ + (s + 1)) * G4N_ + nc0 + cu;
                pfn[0] = __ldg(xp);
                pfn[1] = __ldg(xp + 512);
                pfn[2] = __ldg(xp + 1024);
                pfn[3] = __ldg(xp + 1536);
            } else {
                pfn[0] = lbr[0]; pfn[1] = lbr[1]; pfn[2] = lbr[2]; pfn[3] = lbr[3];
            }

            float z[4];
#pragma unroll
            for (int q = 0; q < 4; q++) {
                const int n = q * 4 + cu;
                float accv = pf[q];
#pragma unroll
                for (int kk = 0; kk < 8; kk++)
                    accv += psum[(kk * 16 + n) * PS_ + b];
                z[q] = accv;
            }
            float ii = sigf(z[0]), ff = sigf(z[1]);
            float gg = tanhf(z[2]), oo = sigf(z[3]);
            cst = ff * cst + ii * gg;
            float hn = oo * tanhf(cst);
            d_h[(s + 1) & 1][(size_t)b * N_ + nc0 + cu] = hn;
            if (s >= H_)
                preds[((size_t)b * P_ + (s - H_)) * N_ + nc0 + cu] = hn;

            pf[0] = pfn[0]; pf[1] = pfn[1]; pf[2] = pfn[2]; pf[3] = pfn[3];
        }
        grid_barrier();
    }
}

// ======================================================================
// launch
// ======================================================================
extern "C" void kernel_launch(void* const* d_in, const int* in_sizes, int n_in,
                              void* d_out, int out_size)
{
    const float* x       = (const float*)d_in[0];
    const float* conv_w  = (const float*)d_in[1];
    const float* conv_b  = (const float*)d_in[2];
    const float* lstm_k  = (const float*)d_in[3];
    const float* lstm_rk = (const float*)d_in[4];
    const float* lstm_b  = (const float*)d_in[5];
    const float* dense_w = (const float*)d_in[6];
    const float* dense_b = (const float*)d_in[7];
    float* out = (float*)d_out;

    float *xr, *xk, *wdec, *preds;
    cudaGetSymbolAddress((void**)&xr,    d_xr);
    cudaGetSymbolAddress((void**)&xk,    d_xk);
    cudaGetSymbolAddress((void**)&wdec,  d_wdec);
    cudaGetSymbolAddress((void**)&preds, d_preds);

    const int RSMEM = (12288 + 12288 + 16512 + 4608) * 4;  // 182784 B
    cudaFuncSetAttribute(recurrence, cudaFuncAttributeMaxDynamicSharedMemorySize, RSMEM);

    // 1) xr = reshape(x) @ conv_w + conv_b     [5376,4096]x[4096,512]
    {
        dim3 grid(N_ / BN, MR_ / BM);
        gemm_tf32<<<grid, 256>>>(x, conv_w, conv_b, xr, MR_, N_, KIN_);
    }
    // 2) xk = xr @ lstm_k + lstm_b             [5376,512]x[512,2048]
    {
        dim3 grid(G4N_ / BN, MR_ / BM);
        gemm_tf32<<<grid, 256>>>(xr, lstm_k, lstm_b, xk, MR_, G4N_, N_);
    }
    // 3) Wdec = lstm_k + lstm_rk
    {
        int n4 = (N_ * G4N_) / 4;
        add_w<<<(n4 + 255) / 256, 256>>>(lstm_k, lstm_rk, wdec, n4);
    }
    // 4) encoder (168 steps) + decoder (24 steps), persistent
    recurrence<<<RGRID, 512, RSMEM>>>(lstm_rk, wdec, xk, lstm_b, preds);
    // 5) out = preds @ dense_w + dense_b       [768,512]x[512,512]
    {
        dim3 grid(N_ / BN, (B_ * P_) / BM);
        gemm_tf32<<<grid, 256>>>(preds, dense_w, dense_b, out, B_ * P_, N_, N_);
    }
}